// round 3
// baseline (speedup 1.0000x reference)
#include <cuda_runtime.h>
#include <math.h>

#define BN 1024
#define DN 128
#define HN 128
#define LN_EPS 1e-5f

__device__ float g_dm[BN * DN];

typedef unsigned long long ull;

// ===========================================================================
// K1: per-column mean |x_i - x_j| via hybrid shfl/smem bitonic sort.
// 128 blocks (one per column), 512 threads, 2 keys per thread in registers.
// Thread (w, lane) owns positions p0 = 64w+lane, p1 = p0+32.
// ===========================================================================
__device__ __forceinline__ ull u64min(ull a, ull b) { return a < b ? a : b; }
__device__ __forceinline__ ull u64max(ull a, ull b) { return a < b ? b : a; }

__global__ __launch_bounds__(512) void col_absdiff_mean_kernel(
    const float* __restrict__ x, float* __restrict__ dm)
{
    __shared__ ull sk[BN];
    __shared__ float wsum[16];

    const int d = blockIdx.x;
    const int t = threadIdx.x;
    const int lane = t & 31;
    const int w = t >> 5;
    const int p0 = (w << 6) + lane;
    const int p1 = p0 + 32;

    // load + order-preserving encode
    unsigned u0 = __float_as_uint(x[p0 * DN + d]);
    unsigned u1 = __float_as_uint(x[p1 * DN + d]);
    u0 ^= (u0 & 0x80000000u) ? 0xFFFFFFFFu : 0x80000000u;
    u1 ^= (u1 & 0x80000000u) ? 0xFFFFFFFFu : 0x80000000u;
    ull r0 = ((ull)u0 << 32) | (unsigned)p0;
    ull r1 = ((ull)u1 << 32) | (unsigned)p1;

    // ---- phase A: k = 2..64, all in registers/shfl ----
    #pragma unroll
    for (int k = 2; k <= 64; k <<= 1) {
        #pragma unroll
        for (int j = k >> 1; j > 0; j >>= 1) {
            if (j == 32) {
                bool up = ((p0 & k) == 0);
                ull lo = u64min(r0, r1), hi = u64max(r0, r1);
                r0 = up ? lo : hi;
                r1 = up ? hi : lo;
            } else {
                bool up0 = ((p0 & k) == 0);
                bool km0 = (((p0 & j) == 0) == up0);
                ull o0 = __shfl_xor_sync(0xffffffffu, r0, j);
                r0 = km0 ? u64min(r0, o0) : u64max(r0, o0);
                bool up1 = ((p1 & k) == 0);
                bool km1 = (((p1 & j) == 0) == up1);
                ull o1 = __shfl_xor_sync(0xffffffffu, r1, j);
                r1 = km1 ? u64min(r1, o1) : u64max(r1, o1);
            }
        }
    }

    // ---- phase B: k = 128..1024; j>=64 in smem, j<=32 in registers ----
    #pragma unroll
    for (int k = 128; k <= 1024; k <<= 1) {
        sk[p0] = r0;
        sk[p1] = r1;
        __syncthreads();
        for (int j = k >> 1; j >= 64; j >>= 1) {
            int i = ((t & ~(j - 1)) << 1) | (t & (j - 1));
            int ixj = i | j;
            ull a = sk[i];
            ull b = sk[ixj];
            bool up = ((i & k) == 0);
            if ((a > b) == up) { sk[i] = b; sk[ixj] = a; }
            __syncthreads();
        }
        r0 = sk[p0];
        r1 = sk[p1];
        bool up = ((p0 & k) == 0);   // same for p1 since k >= 128
        // j = 32 (register pair)
        {
            ull lo = u64min(r0, r1), hi = u64max(r0, r1);
            r0 = up ? lo : hi;
            r1 = up ? hi : lo;
        }
        #pragma unroll
        for (int j = 16; j > 0; j >>= 1) {
            bool km = (((p0 & j) == 0) == up);   // p0&j == p1&j for j<=16
            ull o0 = __shfl_xor_sync(0xffffffffu, r0, j);
            r0 = km ? u64min(r0, o0) : u64max(r0, o0);
            ull o1 = __shfl_xor_sync(0xffffffffu, r1, j);
            r1 = km ? u64min(r1, o1) : u64max(r1, o1);
        }
    }

    // ---- decode sorted values + prefix sums ----
    unsigned e0 = (unsigned)(r0 >> 32);
    unsigned e1 = (unsigned)(r1 >> 32);
    e0 ^= (e0 & 0x80000000u) ? 0x80000000u : 0xFFFFFFFFu;
    e1 ^= (e1 & 0x80000000u) ? 0x80000000u : 0xFFFFFFFFu;
    float v0 = __uint_as_float(e0);
    float v1 = __uint_as_float(e1);
    unsigned idx0 = (unsigned)r0;
    unsigned idx1 = (unsigned)r1;

    // warp inclusive scans (positions: lanes 0..31 then lanes 32..63 of block)
    float s0 = v0;
    #pragma unroll
    for (int o = 1; o < 32; o <<= 1) {
        float n = __shfl_up_sync(0xffffffffu, s0, o);
        if (lane >= o) s0 += n;
    }
    float T0 = __shfl_sync(0xffffffffu, s0, 31);
    float s1 = v1;
    #pragma unroll
    for (int o = 1; o < 32; o <<= 1) {
        float n = __shfl_up_sync(0xffffffffu, s1, o);
        if (lane >= o) s1 += n;
    }
    float T1 = __shfl_sync(0xffffffffu, s1, 31);
    if (lane == 0) wsum[w] = T0 + T1;
    __syncthreads();
    if (t < 16) {
        float v = wsum[t];
        #pragma unroll
        for (int o = 1; o < 16; o <<= 1) {
            float n = __shfl_up_sync(0x0000ffffu, v, o);
            if (t >= o) v += n;
        }
        wsum[t] = v;
    }
    __syncthreads();
    const float S = wsum[15];
    const float wexcl = (w == 0) ? 0.0f : wsum[w - 1];
    float inc0 = wexcl + s0;
    float inc1 = wexcl + T0 + s1;

    float o0 = v0 * (float)(2 * (p0 + 1) - BN) + S - 2.0f * inc0;
    float o1 = v1 * (float)(2 * (p1 + 1) - BN) + S - 2.0f * inc1;
    dm[idx0 * DN + d] = o0 * (1.0f / (float)BN);
    dm[idx1 * DN + d] = o1 * (1.0f / (float)BN);
}

// ===========================================================================
// K3: fused tail. 128 blocks x 8 rows, 1024 threads.
// col = t>>3 (0..127), g = t&7 (16 k-values each: [16g, 16g+16)).
// Weights read directly from global (LDG.128, L2-shared, each elem once/CTA).
// Cross-g combine: 7-shfl warp butterfly (lanes g, g^1, g^2, g^4 adjacent).
// Input smem layout swizzled: SWZ(k) = (k>>4)*132 + (k&15)*8  -> CF LDS.128.
// ===========================================================================
#define SWZ(k) ((((k) >> 4) * 132) + (((k) & 15) << 3))

__device__ __forceinline__ ull fma2(ull a, ull b, ull c) {
    ull d;
    asm("fma.rn.f32x2 %0, %1, %2, %3;" : "=l"(d) : "l"(a), "l"(b), "l"(c));
    return d;
}
__device__ __forceinline__ ull add2(ull a, ull b) {
    ull d;
    asm("add.rn.f32x2 %0, %1, %2;" : "=l"(d) : "l"(a), "l"(b));
    return d;
}
__device__ __forceinline__ ull dup2(float w) {
    ull d;
    asm("mov.b64 %0, {%1, %1};" : "=l"(d) : "r"(__float_as_uint(w)));
    return d;
}

// acc over 16 k-values then butterfly-reduce over g; returns scalar for row g.
__device__ __forceinline__ float mv_combine(
    const float4 w4[4], const float* __restrict__ ip, int g)
{
    ull a0 = 0, a1 = 0, a2 = 0, a3 = 0;
    #pragma unroll
    for (int c = 0; c < 4; c++) {
        float wv[4] = { w4[c].x, w4[c].y, w4[c].z, w4[c].w };
        #pragma unroll
        for (int e = 0; e < 4; e++) {
            int j = c * 4 + e;
            ull w2 = dup2(wv[e]);
            const ulonglong2* p = (const ulonglong2*)(ip + j * 8);
            ulonglong2 q0 = p[0];
            ulonglong2 q1 = p[1];
            a0 = fma2(q0.x, w2, a0);
            a1 = fma2(q0.y, w2, a1);
            a2 = fma2(q1.x, w2, a2);
            a3 = fma2(q1.y, w2, a3);
        }
    }
    // butterfly: end with lane's own row g
    ull sA = (g & 4) ? a0 : a2;
    ull sB = (g & 4) ? a1 : a3;
    ull rA = __shfl_xor_sync(0xffffffffu, sA, 4);
    ull rB = __shfl_xor_sync(0xffffffffu, sB, 4);
    ull kA = (g & 4) ? a2 : a0;
    ull kB = (g & 4) ? a3 : a1;
    a0 = add2(kA, rA);
    a1 = add2(kB, rB);
    ull sC = (g & 2) ? a0 : a1;
    ull rC = __shfl_xor_sync(0xffffffffu, sC, 2);
    ull kC = (g & 2) ? a1 : a0;
    a0 = add2(kC, rC);
    float lo = __uint_as_float((unsigned)a0);
    float hi = __uint_as_float((unsigned)(a0 >> 32));
    float snd = (g & 1) ? lo : hi;
    float rec = __shfl_xor_sync(0xffffffffu, snd, 1);
    return ((g & 1) ? hi : lo) + rec;
}

__global__ __launch_bounds__(1024, 1) void fused_tail_kernel(
    const float* __restrict__ x,
    const float* __restrict__ Wd, const float* __restrict__ bd,
    const float* __restrict__ Wt, const float* __restrict__ bt,
    const float* __restrict__ Wa, const float* __restrict__ ba,
    const float* __restrict__ Wr, const float* __restrict__ br,
    const float* __restrict__ gamma, const float* __restrict__ beta,
    const float* __restrict__ dm,
    float* __restrict__ out)
{
    __shared__ float xs[1056];
    __shared__ float ds[1056];
    __shared__ float hs[1056];
    __shared__ float cb[768];       // Wt | bd | ba | br | gamma | beta
    __shared__ float redS[256];
    __shared__ float redQ[256];
    __shared__ float tau_s[8];
    __shared__ float musig[16];

    const int t = threadIdx.x;
    const int col = t >> 3;
    const int g = t & 7;
    const int lane = t & 31;
    const int warp = t >> 5;
    const int i0 = blockIdx.x * 8;
    const int woff = col * 128 + g * 16;

    // prefetch Wd tile for this thread
    float4 wA[4], wB[4];
    {
        const float4* p = (const float4*)(Wd + woff);
        #pragma unroll
        for (int c = 0; c < 4; c++) wA[c] = p[c];
    }

    // stage x and dm rows into swizzled smem; stage small vectors
    {
        int r = t >> 7, k = t & 127;
        int o = SWZ(k) + r;
        xs[o] = x[(i0 + r) * DN + k];
        ds[o] = dm[(i0 + r) * DN + k];
    }
    if (t < 128)       cb[t] = Wt[t];
    else if (t < 256)  cb[t] = bd[t - 128];
    else if (t < 384)  cb[t] = ba[t - 256];
    else if (t < 512)  cb[t] = br[t - 384];
    else if (t < 640)  cb[t] = gamma[t - 512];
    else if (t < 768)  cb[t] = beta[t - 640];
    __syncthreads();

    // ---- tau per row (threads 0..127; thread = k) ----
    if (t < 128) {
        float wt = cb[t];
        const float* xp = xs + SWZ(t);
        float4 xa = *(const float4*)xp;
        float4 xb = *(const float4*)(xp + 4);
        float pr[8] = { xa.x * wt, xa.y * wt, xa.z * wt, xa.w * wt,
                        xb.x * wt, xb.y * wt, xb.z * wt, xb.w * wt };
        #pragma unroll
        for (int r = 0; r < 8; r++) {
            float v = pr[r];
            #pragma unroll
            for (int o = 16; o; o >>= 1) v += __shfl_xor_sync(0xffffffffu, v, o);
            if (lane == 0) redS[(t >> 5) * 8 + r] = v;
        }
    }
    // prefetch Wa while tau partials land
    {
        const float4* p = (const float4*)(Wa + woff);
        #pragma unroll
        for (int c = 0; c < 4; c++) wB[c] = p[c];
    }
    __syncthreads();
    if (t < 8) {
        float z = redS[t] + redS[8 + t] + redS[16 + t] + redS[24 + t] + bt[0];
        float sp = fmaxf(z, 0.0f) + log1pf(expf(-fabsf(z)));
        tau_s[t] = fmaxf(sp, 0.01f) + 1.0f;
    }
    __syncthreads();

    // ---- matvec 1: d_mean = dm @ Wd^T ; h_mean = (.+bd)/tau ----
    float s1 = mv_combine(wA, ds + 132 * g, g);
    float hm = (s1 + cb[128 + col]) / tau_s[g];
    hs[SWZ(col) + g] = hm;
    // prefetch Wr into wA
    {
        const float4* p = (const float4*)(Wr + woff);
        #pragma unroll
        for (int c = 0; c < 4; c++) wA[c] = p[c];
    }
    __syncthreads();

    // ---- matvec 2: h = relu(hm @ Wa^T + ba) ----
    float s2 = mv_combine(wB, hs + 132 * g, g);
    float h = fmaxf(s2 + cb[256 + col], 0.0f);

    // ---- matvec 3: y = h + x @ Wr^T + br  (xs untouched, no barrier needed) ----
    float s3 = mv_combine(wA, xs + 132 * g, g);
    float y = h + s3 + cb[384 + col];

    // ---- LayerNorm over col per row g ----
    float s = y, qq = y * y;
    s += __shfl_xor_sync(0xffffffffu, s, 8);
    s += __shfl_xor_sync(0xffffffffu, s, 16);
    qq += __shfl_xor_sync(0xffffffffu, qq, 8);
    qq += __shfl_xor_sync(0xffffffffu, qq, 16);
    if (lane < 8) { redS[warp * 8 + g] = s; redQ[warp * 8 + g] = qq; }
    __syncthreads();
    if (t < 8) {
        float ss = 0.0f, qs = 0.0f;
        #pragma unroll
        for (int ww = 0; ww < 32; ww++) { ss += redS[ww * 8 + t]; qs += redQ[ww * 8 + t]; }
        float mu = ss * (1.0f / 128.0f);
        float var = qs * (1.0f / 128.0f) - mu * mu;
        musig[2 * t] = mu;
        musig[2 * t + 1] = rsqrtf(var + LN_EPS);
    }
    __syncthreads();
    out[(i0 + g) * HN + col] =
        (y - musig[2 * g]) * musig[2 * g + 1] * cb[512 + col] + cb[640 + col];
}

// ===========================================================================
extern "C" void kernel_launch(void* const* d_in, const int* in_sizes, int n_in,
                              void* d_out, int out_size)
{
    const float* x     = (const float*)d_in[0];
    const float* Wd    = (const float*)d_in[1];
    const float* bd    = (const float*)d_in[2];
    const float* Wt    = (const float*)d_in[3];
    const float* bt    = (const float*)d_in[4];
    const float* Wa    = (const float*)d_in[5];
    const float* ba    = (const float*)d_in[6];
    const float* Wr    = (const float*)d_in[7];
    const float* br    = (const float*)d_in[8];
    const float* gamma = (const float*)d_in[9];
    const float* beta  = (const float*)d_in[10];
    float* out = (float*)d_out;

    float* dm = nullptr;
    cudaGetSymbolAddress((void**)&dm, g_dm);

    col_absdiff_mean_kernel<<<DN, 512>>>(x, dm);
    fused_tail_kernel<<<BN / 8, 1024>>>(
        x, Wd, bd, Wt, bt, Wa, ba, Wr, br, gamma, beta, dm, out);
}

// round 4
// speedup vs baseline: 1.3814x; 1.3814x over previous
#include <cuda_runtime.h>
#include <math.h>

#define BN 1024
#define DN 128
#define HN 128
#define LN_EPS 1e-5f

__device__ float g_dm[BN * DN];

typedef unsigned long long ull;
typedef unsigned int uint;

// ===========================================================================
// order-preserving float <-> uint encode
// ===========================================================================
__device__ __forceinline__ uint encf(float f) {
    uint u = __float_as_uint(f);
    return u ^ ((u & 0x80000000u) ? 0xFFFFFFFFu : 0x80000000u);
}
__device__ __forceinline__ float decf(uint u) {
    u ^= (u & 0x80000000u) ? 0x80000000u : 0xFFFFFFFFu;
    return __uint_as_float(u);
}

// ===========================================================================
// K1: per-column mean |x_i - x_j|.  32-bit key bitonic sort (hybrid
// shfl/smem) + prefix sums + per-element binary-search rank recovery.
// 128 blocks (one per column), 512 threads, 2 keys/thread.
// ===========================================================================
__global__ __launch_bounds__(512) void col_absdiff_mean_kernel(
    const float* __restrict__ x, float* __restrict__ dm)
{
    __shared__ uint  sv[BN];
    __shared__ float ps[BN];
    __shared__ float wsum[16];

    const int d = blockIdx.x;
    const int t = threadIdx.x;
    const int lane = t & 31;
    const int w = t >> 5;
    const int p0 = (w << 6) + lane;
    const int p1 = p0 + 32;

    const float f0 = x[p0 * DN + d];
    const float f1 = x[p1 * DN + d];
    const uint e0 = encf(f0);
    const uint e1 = encf(f1);
    uint r0 = e0, r1 = e1;

    // ---- phase A: k = 2..64, registers/shfl only ----
    #pragma unroll
    for (int k = 2; k <= 64; k <<= 1) {
        #pragma unroll
        for (int j = k >> 1; j > 0; j >>= 1) {
            if (j == 32) {
                bool up = ((p0 & k) == 0);
                uint lo = min(r0, r1), hi = max(r0, r1);
                r0 = up ? lo : hi;
                r1 = up ? hi : lo;
            } else {
                bool up0 = ((p0 & k) == 0);
                bool km0 = (((p0 & j) == 0) == up0);
                uint o0 = __shfl_xor_sync(0xffffffffu, r0, j);
                r0 = km0 ? min(r0, o0) : max(r0, o0);
                bool up1 = ((p1 & k) == 0);
                bool km1 = (((p1 & j) == 0) == up1);
                uint o1 = __shfl_xor_sync(0xffffffffu, r1, j);
                r1 = km1 ? min(r1, o1) : max(r1, o1);
            }
        }
    }

    // ---- phase B: k = 128..1024; j>=64 via smem, j<=32 via registers ----
    #pragma unroll
    for (int k = 128; k <= 1024; k <<= 1) {
        sv[p0] = r0;
        sv[p1] = r1;
        __syncthreads();
        for (int j = k >> 1; j >= 64; j >>= 1) {
            int i = ((t & ~(j - 1)) << 1) | (t & (j - 1));
            int ixj = i | j;
            uint a = sv[i];
            uint b = sv[ixj];
            bool up = ((i & k) == 0);
            if ((a > b) == up) { sv[i] = b; sv[ixj] = a; }
            __syncthreads();
        }
        r0 = sv[p0];
        r1 = sv[p1];
        bool up = ((p0 & k) == 0);
        {
            uint lo = min(r0, r1), hi = max(r0, r1);
            r0 = up ? lo : hi;
            r1 = up ? hi : lo;
        }
        #pragma unroll
        for (int j = 16; j > 0; j >>= 1) {
            bool km = (((p0 & j) == 0) == up);
            uint o0 = __shfl_xor_sync(0xffffffffu, r0, j);
            r0 = km ? min(r0, o0) : max(r0, o0);
            uint o1 = __shfl_xor_sync(0xffffffffu, r1, j);
            r1 = km ? min(r1, o1) : max(r1, o1);
        }
    }

    // ---- store sorted keys + compute inclusive prefix sums ----
    sv[p0] = r0;
    sv[p1] = r1;
    float v0 = decf(r0);
    float v1 = decf(r1);

    float s0 = v0;
    #pragma unroll
    for (int o = 1; o < 32; o <<= 1) {
        float n = __shfl_up_sync(0xffffffffu, s0, o);
        if (lane >= o) s0 += n;
    }
    float T0 = __shfl_sync(0xffffffffu, s0, 31);
    float s1 = v1;
    #pragma unroll
    for (int o = 1; o < 32; o <<= 1) {
        float n = __shfl_up_sync(0xffffffffu, s1, o);
        if (lane >= o) s1 += n;
    }
    float T1 = __shfl_sync(0xffffffffu, s1, 31);
    if (lane == 0) wsum[w] = T0 + T1;
    __syncthreads();
    if (t < 16) {
        float v = wsum[t];
        #pragma unroll
        for (int o = 1; o < 16; o <<= 1) {
            float n = __shfl_up_sync(0x0000ffffu, v, o);
            if (t >= o) v += n;
        }
        wsum[t] = v;
    }
    __syncthreads();
    const float S = wsum[15];
    const float wexcl = (w == 0) ? 0.0f : wsum[w - 1];
    ps[p0] = wexcl + s0;
    ps[p1] = wexcl + T0 + s1;
    __syncthreads();

    // ---- binary-search rank of each ORIGINAL element; closed-form write ----
    {
        int q = 0;
        #pragma unroll
        for (int st = 512; st > 0; st >>= 1) {
            int nq = q + st;
            if (sv[nq - 1] < e0) q = nq;
        }
        float o = f0 * (float)(2 * (q + 1) - BN) + S - 2.0f * ps[q];
        dm[p0 * DN + d] = o * (1.0f / (float)BN);
    }
    {
        int q = 0;
        #pragma unroll
        for (int st = 512; st > 0; st >>= 1) {
            int nq = q + st;
            if (sv[nq - 1] < e1) q = nq;
        }
        float o = f1 * (float)(2 * (q + 1) - BN) + S - 2.0f * ps[q];
        dm[p1 * DN + d] = o * (1.0f / (float)BN);
    }
}

// ===========================================================================
// K3: fused tail. 128 blocks x 8 rows, 512 threads.
// Thread = (col-group of 4 cols) x (k-chunk of 8 k).  Half-warp = one
// col-group (lanes m=0..15 are the 16 k-chunks).  Inputs in padded smem
// (68 floats per 8-k chunk -> conflict-free LDS.128 with static indexing).
// Weights direct from global (LDG.128, exact, prefetched across matvecs).
// Cross-chunk combine: 4-stage recursive-halving shuffle butterfly.
// ===========================================================================
__device__ __forceinline__ ull fma2(ull a, ull b, ull c) {
    ull d;
    asm("fma.rn.f32x2 %0, %1, %2, %3;" : "=l"(d) : "l"(a), "l"(b), "l"(c));
    return d;
}
__device__ __forceinline__ ull add2(ull a, ull b) {
    ull d;
    asm("add.rn.f32x2 %0, %1, %2;" : "=l"(d) : "l"(a), "l"(b));
    return d;
}
__device__ __forceinline__ ull dup2(float w) {
    ull d;
    asm("mov.b64 %0, {%1, %1};" : "=l"(d) : "r"(__float_as_uint(w)));
    return d;
}

#define CHW 68   /* floats per 8-k chunk (64 data + 4 pad) */
#define IDX(k, r) ((((k) >> 3) * CHW) + (((k) & 7) << 3) + (r))

__device__ __forceinline__ void load_w(const float* __restrict__ W,
                                       int colbase, int k0, float4 wv[8])
{
    #pragma unroll
    for (int c = 0; c < 4; c++) {
        const float4* p = (const float4*)(W + (colbase + c) * DN + k0);
        wv[c * 2]     = p[0];
        wv[c * 2 + 1] = p[1];
    }
}

__device__ __forceinline__ void mv_acc(const float* __restrict__ ip,
                                       const float4 wv[8], ull A[16])
{
    #pragma unroll
    for (int kl = 0; kl < 8; kl++) {
        ulonglong2 q0 = *(const ulonglong2*)(ip + kl * 8);       // rows 0-3
        ulonglong2 q1 = *(const ulonglong2*)(ip + kl * 8 + 4);   // rows 4-7
        #pragma unroll
        for (int c = 0; c < 4; c++) {
            const float* wp = (const float*)&wv[c * 2 + (kl >> 2)];
            ull w2 = dup2(wp[kl & 3]);
            A[c * 4 + 0] = fma2(q0.x, w2, A[c * 4 + 0]);
            A[c * 4 + 1] = fma2(q0.y, w2, A[c * 4 + 1]);
            A[c * 4 + 2] = fma2(q1.x, w2, A[c * 4 + 2]);
            A[c * 4 + 3] = fma2(q1.y, w2, A[c * 4 + 3]);
        }
    }
}

// recursive-halving butterfly over 16 lanes; lane m ends with floats 2m,2m+1
__device__ __forceinline__ ull butterfly16(ull A[16], int m)
{
    #pragma unroll
    for (int j = 0; j < 8; j++) {
        ull snd = (m & 8) ? A[j] : A[j + 8];
        ull rcv = __shfl_xor_sync(0xffffffffu, snd, 8);
        A[j] = add2((m & 8) ? A[j + 8] : A[j], rcv);
    }
    #pragma unroll
    for (int j = 0; j < 4; j++) {
        ull snd = (m & 4) ? A[j] : A[j + 4];
        ull rcv = __shfl_xor_sync(0xffffffffu, snd, 4);
        A[j] = add2((m & 4) ? A[j + 4] : A[j], rcv);
    }
    #pragma unroll
    for (int j = 0; j < 2; j++) {
        ull snd = (m & 2) ? A[j] : A[j + 2];
        ull rcv = __shfl_xor_sync(0xffffffffu, snd, 2);
        A[j] = add2((m & 2) ? A[j + 2] : A[j], rcv);
    }
    {
        ull snd = (m & 1) ? A[0] : A[1];
        ull rcv = __shfl_xor_sync(0xffffffffu, snd, 1);
        A[0] = add2((m & 1) ? A[1] : A[0], rcv);
    }
    return A[0];
}

__global__ __launch_bounds__(512) void fused_tail_kernel(
    const float* __restrict__ x,
    const float* __restrict__ Wd, const float* __restrict__ bd,
    const float* __restrict__ Wt, const float* __restrict__ bt,
    const float* __restrict__ Wa, const float* __restrict__ ba,
    const float* __restrict__ Wr, const float* __restrict__ br,
    const float* __restrict__ gamma, const float* __restrict__ beta,
    const float* __restrict__ dm,
    float* __restrict__ out)
{
    __shared__ __align__(16) float xs[16 * CHW];
    __shared__ __align__(16) float ds[16 * CHW];
    __shared__ __align__(16) float hs[16 * CHW];
    __shared__ float Wt_s[128], bd_s[128], ba_s[128], br_s[128], g_s[128], be_s[128];
    __shared__ float redS[128], redQ[128];
    __shared__ float tau_s[8];
    __shared__ float musig[16];

    const int t = threadIdx.x;
    const int lane = t & 31;
    const int m = lane & 15;
    const int chunk = m;
    const int colbase = (t >> 4) * 4;
    const int k0 = chunk * 8;
    const int i0 = blockIdx.x * 8;
    const int col = colbase + (m >> 2);
    const int r0 = 2 * (m & 3);

    float4 wcur[8], wnxt[8];
    load_w(Wd, colbase, k0, wcur);

    // ---- stage inputs ----
    #pragma unroll
    for (int it = 0; it < 2; it++) {
        int e = t + it * 512;
        int r = e >> 7, k = e & 127;
        int o = IDX(k, r);
        xs[o] = x[(i0 + r) * DN + k];
        ds[o] = dm[(i0 + r) * DN + k];
    }
    if (t < 128)       { Wt_s[t] = Wt[t];             g_s[t] = gamma[t]; }
    else if (t < 256)  { bd_s[t - 128] = bd[t - 128]; be_s[t - 128] = beta[t - 128]; }
    else if (t < 384)  { ba_s[t - 256] = ba[t - 256]; }
    else               { br_s[t - 384] = br[t - 384]; }
    __syncthreads();

    // ---- tau per row (threads 0..127 = 128 k's) ----
    if (t < 128) {
        int o = IDX(t, 0);
        float4 xa = *(const float4*)(xs + o);
        float4 xb = *(const float4*)(xs + o + 4);
        float wt = Wt_s[t];
        float pr[8] = { xa.x * wt, xa.y * wt, xa.z * wt, xa.w * wt,
                        xb.x * wt, xb.y * wt, xb.z * wt, xb.w * wt };
        #pragma unroll
        for (int r = 0; r < 8; r++) {
            float v = pr[r];
            #pragma unroll
            for (int o2 = 16; o2; o2 >>= 1) v += __shfl_xor_sync(0xffffffffu, v, o2);
            if (lane == 0) redS[(t >> 5) * 8 + r] = v;
        }
    }
    __syncthreads();
    if (t < 8) {
        float z = redS[t] + redS[8 + t] + redS[16 + t] + redS[24 + t] + bt[0];
        float sp = fmaxf(z, 0.0f) + log1pf(expf(-fabsf(z)));
        tau_s[t] = fmaxf(sp, 0.01f) + 1.0f;
    }
    __syncthreads();

    ull A[16];

    // ================= matvec 1: d_mean = dm @ Wd^T ; h_mean =================
    #pragma unroll
    for (int i = 0; i < 16; i++) A[i] = 0ull;
    mv_acc(ds + chunk * CHW, wcur, A);
    load_w(Wa, colbase, k0, wnxt);
    ull red = butterfly16(A, m);
    {
        float v0 = __uint_as_float((uint)red);
        float v1 = __uint_as_float((uint)(red >> 32));
        float bdv = bd_s[col];
        float hm0 = (v0 + bdv) / tau_s[r0];
        float hm1 = (v1 + bdv) / tau_s[r0 + 1];
        *(float2*)(hs + IDX(col, r0)) = make_float2(hm0, hm1);
    }
    __syncthreads();

    // ================= matvec 2: h = relu(hm @ Wa^T + ba) =================
    #pragma unroll
    for (int i = 0; i < 16; i++) A[i] = 0ull;
    mv_acc(hs + chunk * CHW, wnxt, A);
    load_w(Wr, colbase, k0, wcur);
    red = butterfly16(A, m);
    float bav = ba_s[col];
    float h0 = fmaxf(__uint_as_float((uint)red) + bav, 0.0f);
    float h1 = fmaxf(__uint_as_float((uint)(red >> 32)) + bav, 0.0f);

    // ================= matvec 3: y = h + x @ Wr^T + br =================
    #pragma unroll
    for (int i = 0; i < 16; i++) A[i] = 0ull;
    mv_acc(xs + chunk * CHW, wcur, A);
    red = butterfly16(A, m);
    float brv = br_s[col];
    float y0 = h0 + __uint_as_float((uint)red) + brv;
    float y1 = h1 + __uint_as_float((uint)(red >> 32)) + brv;

    // ---- LayerNorm reductions ----
    float s0 = y0, q0 = y0 * y0, s1 = y1, q1 = y1 * y1;
    #pragma unroll
    for (int mk = 4; mk <= 16; mk <<= 1) {
        s0 += __shfl_xor_sync(0xffffffffu, s0, mk);
        q0 += __shfl_xor_sync(0xffffffffu, q0, mk);
        s1 += __shfl_xor_sync(0xffffffffu, s1, mk);
        q1 += __shfl_xor_sync(0xffffffffu, q1, mk);
    }
    if (lane < 4) {
        int wp = t >> 5;
        redS[wp * 8 + r0] = s0;     redQ[wp * 8 + r0] = q0;
        redS[wp * 8 + r0 + 1] = s1; redQ[wp * 8 + r0 + 1] = q1;
    }
    __syncthreads();
    if (t < 8) {
        float ss = 0.0f, qs = 0.0f;
        #pragma unroll
        for (int wp = 0; wp < 16; wp++) { ss += redS[wp * 8 + t]; qs += redQ[wp * 8 + t]; }
        float mu = ss * (1.0f / 128.0f);
        float var = qs * (1.0f / 128.0f) - mu * mu;
        musig[2 * t] = mu;
        musig[2 * t + 1] = rsqrtf(var + LN_EPS);
    }
    __syncthreads();
    float gv = g_s[col], bv = be_s[col];
    out[(i0 + r0) * HN + col]     = (y0 - musig[2 * r0]) * musig[2 * r0 + 1] * gv + bv;
    out[(i0 + r0 + 1) * HN + col] = (y1 - musig[2 * r0 + 2]) * musig[2 * r0 + 3] * gv + bv;
}

// ===========================================================================
extern "C" void kernel_launch(void* const* d_in, const int* in_sizes, int n_in,
                              void* d_out, int out_size)
{
    const float* x     = (const float*)d_in[0];
    const float* Wd    = (const float*)d_in[1];
    const float* bd    = (const float*)d_in[2];
    const float* Wt    = (const float*)d_in[3];
    const float* bt    = (const float*)d_in[4];
    const float* Wa    = (const float*)d_in[5];
    const float* ba    = (const float*)d_in[6];
    const float* Wr    = (const float*)d_in[7];
    const float* br    = (const float*)d_in[8];
    const float* gamma = (const float*)d_in[9];
    const float* beta  = (const float*)d_in[10];
    float* out = (float*)d_out;

    float* dm = nullptr;
    cudaGetSymbolAddress((void**)&dm, g_dm);

    col_absdiff_mean_kernel<<<DN, 512>>>(x, dm);
    fused_tail_kernel<<<BN / 8, 512>>>(
        x, Wd, bd, Wt, bt, Wa, ba, Wr, br, gamma, beta, dm, out);
}